// round 2
// baseline (speedup 1.0000x reference)
#include <cuda_runtime.h>
#include <cuda_bf16.h>

// Problem constants
#define BB 4
#define SS 2048
#define EE 1024
#define HH 16
#define DD 64
#define MM (BB*SS)   // 8192 rows of x

// Scratch: Q/K/V in (B,H,S,D) layout. 3 * 32MB of static device memory.
__device__ float g_Q[(size_t)BB*HH*SS*DD];
__device__ float g_K[(size_t)BB*HH*SS*DD];
__device__ float g_V[(size_t)BB*HH*SS*DD];

// ---------------------------------------------------------------------------
// Kernel 1: fused QKV projection.  Y = X @ W + b, scattered to (B,H,S,D).
// blockIdx.z selects {Q,K,V}.  128x128 tile, BK=16, 256 threads, 8x8/thread.
// ---------------------------------------------------------------------------
#define BM 128
#define BN 128
#define BK 16
#define TM 8
#define TN 8
#define AS_STRIDE (BM + 4)   // pad to soften transposed-store bank conflicts

__global__ __launch_bounds__(256) void qkv_gemm_kernel(
    const float* __restrict__ X,
    const float* __restrict__ Wq, const float* __restrict__ bq,
    const float* __restrict__ Wk, const float* __restrict__ bk,
    const float* __restrict__ Wv, const float* __restrict__ bv)
{
    __shared__ float As[BK][AS_STRIDE];   // A transposed: As[k][m]
    __shared__ float Bs[BK][BN];          // B direct:     Bs[k][n]

    const int which = blockIdx.z;
    const float* __restrict__ W    = (which == 0) ? Wq : (which == 1) ? Wk : Wv;
    const float* __restrict__ bias = (which == 0) ? bq : (which == 1) ? bk : bv;
    float* __restrict__ dst        = (which == 0) ? g_Q : (which == 1) ? g_K : g_V;

    const int tid = threadIdx.x;
    const int m0 = blockIdx.y * BM;
    const int n0 = blockIdx.x * BN;

    // global->shared load mapping
    const int a_row  = tid >> 2;          // 0..63 (two passes: +0, +64)
    const int a_col4 = (tid & 3) * 4;     // 0,4,8,12
    const int b_row  = tid >> 5;          // 0..7  (two passes: +0, +8)
    const int b_col4 = (tid & 31) * 4;    // 0..124

    const int ty = tid >> 4;              // 0..15 -> row block of 8
    const int tx = tid & 15;              // 0..15 -> col block of 8

    float acc[TM][TN];
    #pragma unroll
    for (int i = 0; i < TM; i++)
        #pragma unroll
        for (int j = 0; j < TN; j++)
            acc[i][j] = 0.f;

    for (int k0 = 0; k0 < EE; k0 += BK) {
        // ---- load A tile (128x16) transposed into smem ----
        float4 av0 = *(const float4*)&X[(size_t)(m0 + a_row     ) * EE + k0 + a_col4];
        float4 av1 = *(const float4*)&X[(size_t)(m0 + a_row + 64) * EE + k0 + a_col4];
        As[a_col4 + 0][a_row]      = av0.x;
        As[a_col4 + 1][a_row]      = av0.y;
        As[a_col4 + 2][a_row]      = av0.z;
        As[a_col4 + 3][a_row]      = av0.w;
        As[a_col4 + 0][a_row + 64] = av1.x;
        As[a_col4 + 1][a_row + 64] = av1.y;
        As[a_col4 + 2][a_row + 64] = av1.z;
        As[a_col4 + 3][a_row + 64] = av1.w;
        // ---- load B tile (16x128) ----
        float4 bv0 = *(const float4*)&W[(size_t)(k0 + b_row    ) * EE + n0 + b_col4];
        float4 bv1 = *(const float4*)&W[(size_t)(k0 + b_row + 8) * EE + n0 + b_col4];
        *(float4*)&Bs[b_row    ][b_col4] = bv0;
        *(float4*)&Bs[b_row + 8][b_col4] = bv1;
        __syncthreads();

        #pragma unroll
        for (int k = 0; k < BK; k++) {
            float a[TM], b[TN];
            *(float4*)&a[0] = *(const float4*)&As[k][ty * TM];
            *(float4*)&a[4] = *(const float4*)&As[k][ty * TM + 4];
            *(float4*)&b[0] = *(const float4*)&Bs[k][tx * TN];
            *(float4*)&b[4] = *(const float4*)&Bs[k][tx * TN + 4];
            #pragma unroll
            for (int i = 0; i < TM; i++)
                #pragma unroll
                for (int j = 0; j < TN; j++)
                    acc[i][j] += a[i] * b[j];
        }
        __syncthreads();
    }

    // epilogue: add bias, scatter to (B,H,S,D)
    #pragma unroll
    for (int i = 0; i < TM; i++) {
        const int m = m0 + ty * TM + i;
        const int bidx = m >> 11;          // m / SS
        const int s    = m & (SS - 1);
        #pragma unroll
        for (int j = 0; j < TN; j++) {
            const int n = n0 + tx * TN + j;
            const int h = n >> 6;          // n / DD
            const int d = n & (DD - 1);
            dst[(((size_t)bidx * HH + h) * SS + s) * DD + d] = acc[i][j] + bias[n];
        }
    }
}

// ---------------------------------------------------------------------------
// Kernel 2: flash attention, fp32.  One q-row per thread (row fully
// thread-local => no cross-thread softmax reductions).  128 threads/block,
// K/V streamed through smem in 32-row tiles, broadcast LDS reads.
// ---------------------------------------------------------------------------
#define TKV 32

__global__ __launch_bounds__(128) void attn_kernel(float* __restrict__ out)
{
    __shared__ float Ks[TKV][DD];
    __shared__ float Vs[TKV][DD];

    const int tid = threadIdx.x;
    const int bh  = blockIdx.y;                 // 0..63
    const int row = blockIdx.x * 128 + tid;     // q row within (b,h)

    const float* __restrict__ Qp = g_Q + ((size_t)bh * SS + row) * DD;
    const float* __restrict__ Kp = g_K + (size_t)bh * SS * DD;
    const float* __restrict__ Vp = g_V + (size_t)bh * SS * DD;

    // q row in registers, pre-scaled by 1/sqrt(D)
    const float scale = 0.125f;  // 1/sqrt(64)
    float4 q[16];
    #pragma unroll
    for (int i = 0; i < 16; i++) {
        float4 v = *(const float4*)&Qp[i * 4];
        v.x *= scale; v.y *= scale; v.z *= scale; v.w *= scale;
        q[i] = v;
    }

    float4 o[16];
    #pragma unroll
    for (int i = 0; i < 16; i++) o[i] = make_float4(0.f, 0.f, 0.f, 0.f);
    float mrow = -1e30f;
    float l = 0.f;

    for (int kt = 0; kt < SS; kt += TKV) {
        __syncthreads();   // previous tile fully consumed before overwrite
        // cooperative tile load: TKV*DD = 2048 floats = 512 float4, 4/thread
        #pragma unroll
        for (int i = 0; i < 4; i++) {
            const int idx = tid + i * 128;
            ((float4*)&Ks[0][0])[idx] = ((const float4*)(Kp + (size_t)kt * DD))[idx];
            ((float4*)&Vs[0][0])[idx] = ((const float4*)(Vp + (size_t)kt * DD))[idx];
        }
        __syncthreads();

        // scores for this tile (thread-local row)
        float s[TKV];
        float tmax = -1e30f;
        #pragma unroll
        for (int j = 0; j < TKV; j++) {
            float4 a = make_float4(0.f, 0.f, 0.f, 0.f);
            #pragma unroll
            for (int d4 = 0; d4 < 16; d4++) {
                float4 kv = *(const float4*)&Ks[j][d4 * 4];
                a.x += q[d4].x * kv.x;
                a.y += q[d4].y * kv.y;
                a.z += q[d4].z * kv.z;
                a.w += q[d4].w * kv.w;
            }
            const float sj = (a.x + a.y) + (a.z + a.w);
            s[j] = sj;
            tmax = fmaxf(tmax, sj);
        }

        // online softmax update
        const float mnew = fmaxf(mrow, tmax);
        const float corr = __expf(mrow - mnew);
        l *= corr;
        #pragma unroll
        for (int i = 0; i < 16; i++) {
            o[i].x *= corr; o[i].y *= corr; o[i].z *= corr; o[i].w *= corr;
        }
        mrow = mnew;

        #pragma unroll
        for (int j = 0; j < TKV; j++) {
            const float p = __expf(s[j] - mnew);
            l += p;
            #pragma unroll
            for (int d4 = 0; d4 < 16; d4++) {
                float4 vv = *(const float4*)&Vs[j][d4 * 4];
                o[d4].x += p * vv.x;
                o[d4].y += p * vv.y;
                o[d4].z += p * vv.z;
                o[d4].w += p * vv.w;
            }
        }
    }

    // write output: (B,S,E) with E-slice at h*DD
    const float inv = 1.f / l;
    const int b = bh / HH;
    const int h = bh % HH;
    float* __restrict__ op = out + ((size_t)(b * SS + row)) * EE + h * DD;
    #pragma unroll
    for (int i = 0; i < 16; i++) {
        float4 r;
        r.x = o[i].x * inv; r.y = o[i].y * inv;
        r.z = o[i].z * inv; r.w = o[i].w * inv;
        *(float4*)&op[i * 4] = r;
    }
}

// ---------------------------------------------------------------------------
extern "C" void kernel_launch(void* const* d_in, const int* in_sizes, int n_in,
                              void* d_out, int out_size)
{
    const float* x  = (const float*)d_in[0];
    const float* Wq = (const float*)d_in[1];
    const float* bq = (const float*)d_in[2];
    const float* Wk = (const float*)d_in[3];
    const float* bk = (const float*)d_in[4];
    const float* Wv = (const float*)d_in[5];
    const float* bv = (const float*)d_in[6];
    float* out = (float*)d_out;

    dim3 g1(EE / BN, MM / BM, 3);   // (8, 64, 3)
    qkv_gemm_kernel<<<g1, 256>>>(x, Wq, bq, Wk, bk, Wv, bv);

    dim3 g2(SS / 128, BB * HH);     // (16, 64)
    attn_kernel<<<g2, 128>>>(out);
}

// round 6
// speedup vs baseline: 1.2361x; 1.2361x over previous
#include <cuda_runtime.h>
#include <cuda_bf16.h>
#include <cstdint>

// Problem constants
#define BB 4
#define SS 2048
#define EE 1024
#define HH 16
#define DD 64
#define MM (BB*SS)   // 8192 rows of x

// Scratch: Q/K/V in (B,H,S,D) layout.
__device__ float g_Q[(size_t)BB*HH*SS*DD];
__device__ float g_K[(size_t)BB*HH*SS*DD];
__device__ float g_V[(size_t)BB*HH*SS*DD];

// ---------------------------------------------------------------------------
// Kernel 1: fused QKV projection (R1 SIMT fp32, known good).
// ---------------------------------------------------------------------------
#define BM 128
#define BN 128
#define BK 16
#define TM 8
#define TN 8
#define AS_STRIDE (BM + 4)

__global__ __launch_bounds__(256) void qkv_gemm_kernel(
    const float* __restrict__ X,
    const float* __restrict__ Wq, const float* __restrict__ bq,
    const float* __restrict__ Wk, const float* __restrict__ bk,
    const float* __restrict__ Wv, const float* __restrict__ bv)
{
    __shared__ float As[BK][AS_STRIDE];
    __shared__ float Bs[BK][BN];

    const int which = blockIdx.z;
    const float* __restrict__ W    = (which == 0) ? Wq : (which == 1) ? Wk : Wv;
    const float* __restrict__ bias = (which == 0) ? bq : (which == 1) ? bk : bv;
    float* __restrict__ dst        = (which == 0) ? g_Q : (which == 1) ? g_K : g_V;

    const int tid = threadIdx.x;
    const int m0 = blockIdx.y * BM;
    const int n0 = blockIdx.x * BN;

    const int a_row  = tid >> 2;
    const int a_col4 = (tid & 3) * 4;
    const int b_row  = tid >> 5;
    const int b_col4 = (tid & 31) * 4;

    const int ty = tid >> 4;
    const int tx = tid & 15;

    float acc[TM][TN];
    #pragma unroll
    for (int i = 0; i < TM; i++)
        #pragma unroll
        for (int j = 0; j < TN; j++)
            acc[i][j] = 0.f;

    for (int k0 = 0; k0 < EE; k0 += BK) {
        float4 av0 = *(const float4*)&X[(size_t)(m0 + a_row     ) * EE + k0 + a_col4];
        float4 av1 = *(const float4*)&X[(size_t)(m0 + a_row + 64) * EE + k0 + a_col4];
        As[a_col4 + 0][a_row]      = av0.x;
        As[a_col4 + 1][a_row]      = av0.y;
        As[a_col4 + 2][a_row]      = av0.z;
        As[a_col4 + 3][a_row]      = av0.w;
        As[a_col4 + 0][a_row + 64] = av1.x;
        As[a_col4 + 1][a_row + 64] = av1.y;
        As[a_col4 + 2][a_row + 64] = av1.z;
        As[a_col4 + 3][a_row + 64] = av1.w;
        float4 bv0 = *(const float4*)&W[(size_t)(k0 + b_row    ) * EE + n0 + b_col4];
        float4 bv1 = *(const float4*)&W[(size_t)(k0 + b_row + 8) * EE + n0 + b_col4];
        *(float4*)&Bs[b_row    ][b_col4] = bv0;
        *(float4*)&Bs[b_row + 8][b_col4] = bv1;
        __syncthreads();

        #pragma unroll
        for (int k = 0; k < BK; k++) {
            float a[TM], b[TN];
            *(float4*)&a[0] = *(const float4*)&As[k][ty * TM];
            *(float4*)&a[4] = *(const float4*)&As[k][ty * TM + 4];
            *(float4*)&b[0] = *(const float4*)&Bs[k][tx * TN];
            *(float4*)&b[4] = *(const float4*)&Bs[k][tx * TN + 4];
            #pragma unroll
            for (int i = 0; i < TM; i++)
                #pragma unroll
                for (int j = 0; j < TN; j++)
                    acc[i][j] += a[i] * b[j];
        }
        __syncthreads();
    }

    #pragma unroll
    for (int i = 0; i < TM; i++) {
        const int m = m0 + ty * TM + i;
        const int bidx = m >> 11;
        const int s    = m & (SS - 1);
        #pragma unroll
        for (int j = 0; j < TN; j++) {
            const int n = n0 + tx * TN + j;
            const int h = n >> 6;
            const int d = n & (DD - 1);
            dst[(((size_t)bidx * HH + h) * SS + s) * DD + d] = acc[i][j] + bias[n];
        }
    }
}

// ---------------------------------------------------------------------------
// Kernel 2: GEMM-style two-matmul flash attention.
// 256 threads (16x16). Q tile 128 rows, KV tile 64 rows.
// Thread (ty,tx) owns an 8x4 fragment: rows ty*8..+8, cols tx*4..+4.
// Smem: Qst[d][m] (transposed, scaled), Kst[d][j] (transposed), Vs[j][d],
//       Pst[j][m] (transposed P for the PV GEMM).
// Softmax row stats via 16-lane shfl.bfly (threads sharing ty are 16
// consecutive lanes within one warp).
// ---------------------------------------------------------------------------
#define AT   256
#define QTL  128
#define JTL  64
#define QS   132   // Qst/Pst row stride (floats); 132*4=528B, 16B aligned
#define KS   68    // Kst/Vs  row stride (floats); 68*4=272B, 16B aligned

#define QST(d, m) sm_q[(size_t)(d) * QS + (m)]
#define PST(j, m) sm_p[(size_t)(j) * QS + (m)]
#define KST(d, j) sm_k[(size_t)(d) * KS + (j)]
#define VSM(j, d) sm_v[(size_t)(j) * KS + (d)]

#define ATT_SMEM ((DD * QS + JTL * QS + DD * KS + JTL * KS) * 4)  // 102400 B

__global__ __launch_bounds__(AT) void attn_kernel(float* __restrict__ out)
{
    extern __shared__ float sm[];
    float* sm_q = sm;                       // 64*132
    float* sm_p = sm_q + DD * QS;           // 64*132
    float* sm_k = sm_p + (size_t)JTL * QS;  // 64*68
    float* sm_v = sm_k + (size_t)DD * KS;   // 64*68

    const int tid = threadIdx.x;
    const int ty  = tid >> 4;      // 0..15
    const int tx  = tid & 15;      // 0..15
    const int bh  = blockIdx.y;    // 0..63
    const int q0  = blockIdx.x * QTL;

    const float* __restrict__ Qp = g_Q + (size_t)bh * SS * DD;
    const float* __restrict__ Kp = g_K + (size_t)bh * SS * DD;
    const float* __restrict__ Vp = g_V + (size_t)bh * SS * DD;

    // ---- load Q tile, transposed + pre-scaled: Qst[d][m] ----
    {
        const int m  = tid >> 1;               // 0..127
        const int db = (tid & 1) * 32;         // half-row per thread
        #pragma unroll
        for (int i = 0; i < 8; i++) {
            float4 v = *(const float4*)&Qp[(size_t)(q0 + m) * DD + db + i * 4];
            const int d = db + i * 4;
            QST(d + 0, m) = v.x * 0.125f;
            QST(d + 1, m) = v.y * 0.125f;
            QST(d + 2, m) = v.z * 0.125f;
            QST(d + 3, m) = v.w * 0.125f;
        }
    }

    float o[8][4];
    float mrow[8], lrow[8];
    #pragma unroll
    for (int i = 0; i < 8; i++) {
        mrow[i] = -1e30f;
        lrow[i] = 0.f;
        #pragma unroll
        for (int jj = 0; jj < 4; jj++) o[i][jj] = 0.f;
    }

    for (int kt = 0; kt < SS; kt += JTL) {
        __syncthreads();   // Kst/Vs/Pst free (prev tile PV done)

        // ---- load K (transposed) and V (row-major) tiles ----
        {
            const int j  = tid >> 2;           // 0..63
            const int db = (tid & 3) * 16;
            #pragma unroll
            for (int i = 0; i < 4; i++) {
                const int d = db + i * 4;
                float4 kv = *(const float4*)&Kp[(size_t)(kt + j) * DD + d];
                KST(d + 0, j) = kv.x;
                KST(d + 1, j) = kv.y;
                KST(d + 2, j) = kv.z;
                KST(d + 3, j) = kv.w;
                float4 vv = *(const float4*)&Vp[(size_t)(kt + j) * DD + d];
                *(float4*)&VSM(j, d) = vv;
            }
        }
        __syncthreads();

        // ---- S = Q @ K^T  (c[i][jj] = scores for rows ty*8+i, cols tx*4+jj) ----
        float c[8][4];
        #pragma unroll
        for (int i = 0; i < 8; i++)
            #pragma unroll
            for (int jj = 0; jj < 4; jj++) c[i][jj] = 0.f;

        #pragma unroll 4
        for (int d = 0; d < DD; d++) {
            float a[8], bfr[4];
            *(float4*)&a[0] = *(const float4*)&QST(d, ty * 8);
            *(float4*)&a[4] = *(const float4*)&QST(d, ty * 8 + 4);
            *(float4*)&bfr[0] = *(const float4*)&KST(d, tx * 4);
            #pragma unroll
            for (int i = 0; i < 8; i++)
                #pragma unroll
                for (int jj = 0; jj < 4; jj++)
                    c[i][jj] += a[i] * bfr[jj];
        }

        // ---- online softmax (row stats across the 16 tx lanes) ----
        #pragma unroll
        for (int i = 0; i < 8; i++) {
            float tm = fmaxf(fmaxf(c[i][0], c[i][1]), fmaxf(c[i][2], c[i][3]));
            #pragma unroll
            for (int w = 1; w < 16; w <<= 1)
                tm = fmaxf(tm, __shfl_xor_sync(0xffffffffu, tm, w, 16));
            const float mnew = fmaxf(mrow[i], tm);
            const float corr = __expf(mrow[i] - mnew);
            mrow[i] = mnew;
            float ps = 0.f;
            #pragma unroll
            for (int jj = 0; jj < 4; jj++) {
                const float p = __expf(c[i][jj] - mnew);
                c[i][jj] = p;          // reuse c[] as P fragment
                ps += p;
            }
            #pragma unroll
            for (int w = 1; w < 16; w <<= 1)
                ps += __shfl_xor_sync(0xffffffffu, ps, w, 16);
            lrow[i] = lrow[i] * corr + ps;
            #pragma unroll
            for (int jj = 0; jj < 4; jj++) o[i][jj] *= corr;
        }

        // ---- write P transposed: Pst[j][m] ----
        #pragma unroll
        for (int jj = 0; jj < 4; jj++) {
            float4 p0, p1;
            p0.x = c[0][jj]; p0.y = c[1][jj]; p0.z = c[2][jj]; p0.w = c[3][jj];
            p1.x = c[4][jj]; p1.y = c[5][jj]; p1.z = c[6][jj]; p1.w = c[7][jj];
            *(float4*)&PST(tx * 4 + jj, ty * 8)     = p0;
            *(float4*)&PST(tx * 4 + jj, ty * 8 + 4) = p1;
        }
        __syncthreads();

        // ---- O += P @ V ----
        #pragma unroll 4
        for (int j = 0; j < JTL; j++) {
            float a[8], bfr[4];
            *(float4*)&a[0] = *(const float4*)&PST(j, ty * 8);
            *(float4*)&a[4] = *(const float4*)&PST(j, ty * 8 + 4);
            *(float4*)&bfr[0] = *(const float4*)&VSM(j, tx * 4);
            #pragma unroll
            for (int i = 0; i < 8; i++)
                #pragma unroll
                for (int jj = 0; jj < 4; jj++)
                    o[i][jj] += a[i] * bfr[jj];
        }
    }

    // ---- write output: (B,S,E) with E-slice at h*DD ----
    const int b = bh / HH;
    const int h = bh % HH;
    #pragma unroll
    for (int i = 0; i < 8; i++) {
        const float inv = 1.f / lrow[i];
        const int q = q0 + ty * 8 + i;
        float4 r;
        r.x = o[i][0] * inv; r.y = o[i][1] * inv;
        r.z = o[i][2] * inv; r.w = o[i][3] * inv;
        *(float4*)&out[((size_t)(b * SS + q)) * EE + h * DD + tx * 4] = r;
    }
}

// ---------------------------------------------------------------------------
extern "C" void kernel_launch(void* const* d_in, const int* in_sizes, int n_in,
                              void* d_out, int out_size)
{
    const float* x  = (const float*)d_in[0];
    const float* Wq = (const float*)d_in[1];
    const float* bq = (const float*)d_in[2];
    const float* Wk = (const float*)d_in[3];
    const float* bk = (const float*)d_in[4];
    const float* Wv = (const float*)d_in[5];
    const float* bv = (const float*)d_in[6];
    float* out = (float*)d_out;

    dim3 g1(EE / BN, MM / BM, 3);   // (8, 64, 3)
    qkv_gemm_kernel<<<g1, 256>>>(x, Wq, bq, Wk, bk, Wv, bv);

    cudaFuncSetAttribute(attn_kernel, cudaFuncAttributeMaxDynamicSharedMemorySize, ATT_SMEM);
    dim3 g2(SS / QTL, BB * HH);     // (16, 64)
    attn_kernel<<<g2, AT, ATT_SMEM>>>(out);
}